// round 1
// baseline (speedup 1.0000x reference)
#include <cuda_runtime.h>
#include <math.h>

#define NQ 512
#define NK 1024
#define DIM 256
#define HEADS 8
#define HD 32
#define RPE 512
#define SCALE 0.17677669529663687f

// ---------------- scratch (device globals; no allocation) ----------------
__device__ float g_q[NQ * DIM];
__device__ float g_k[NK * DIM];
__device__ float g_v[NK * DIM];
__device__ float g_x[NQ * DIM];
__device__ float g_tsort[RPE];
__device__ float g_F[HEADS * (RPE + 1)];
__device__ float g_G[HEADS * (RPE + 1)];
__device__ unsigned short g_sidx[NQ * NK];

// ---------------- generic 256x256 GEMM: C[M,256] = A[M,256] @ W + b ------
// sel: 0 -> C=g_q, 1 -> C=g_k, 2 -> C=g_v, 3 -> A=g_x, C=Cext
__global__ void __launch_bounds__(256) gemm256(
    const float* __restrict__ Ain, const float* __restrict__ W,
    const float* __restrict__ bias, float* Cext, int sel) {
  __shared__ float As[16][64];
  __shared__ float Bs[16][64];
  const float* A = (sel == 3) ? (const float*)g_x : Ain;
  float* C = (sel == 0) ? g_q : (sel == 1) ? g_k : (sel == 2) ? g_v : Cext;

  int tid = threadIdx.x;
  int tx = tid % 16, ty = tid / 16;
  int bm = blockIdx.x * 64, bn = blockIdx.y * 64;
  float acc[4][4] = {};

  for (int k0 = 0; k0 < 256; k0 += 16) {
    {
      int r = tid >> 2, c4 = tid & 3;
      float4 av = *(const float4*)&A[(bm + r) * 256 + k0 + c4 * 4];
      As[c4 * 4 + 0][r] = av.x;
      As[c4 * 4 + 1][r] = av.y;
      As[c4 * 4 + 2][r] = av.z;
      As[c4 * 4 + 3][r] = av.w;
    }
    {
      int r = tid >> 4, c4 = tid & 15;
      *(float4*)&Bs[r][c4 * 4] = *(const float4*)&W[(k0 + r) * 256 + bn + c4 * 4];
    }
    __syncthreads();
#pragma unroll
    for (int k = 0; k < 16; k++) {
      float a[4], b[4];
#pragma unroll
      for (int i = 0; i < 4; i++) a[i] = As[k][ty * 4 + i];
#pragma unroll
      for (int j = 0; j < 4; j++) b[j] = Bs[k][tx * 4 + j];
#pragma unroll
      for (int i = 0; i < 4; i++)
#pragma unroll
        for (int j = 0; j < 4; j++) acc[i][j] = fmaf(a[i], b[j], acc[i][j]);
    }
    __syncthreads();
  }
#pragma unroll
  for (int i = 0; i < 4; i++) {
    int row = bm + ty * 4 + i;
#pragma unroll
    for (int j = 0; j < 4; j++) {
      int col = bn + tx * 4 + j;
      C[row * 256 + col] = acc[i][j] + bias[col];
    }
  }
}

// ---------------- CPB precompute: sort thresholds + prefix tables --------
// bias_h(a) = a*F_h[idx] + G_h[idx], idx = #{p : t_sorted[p] < a}
__global__ void cpb_precompute(const float* __restrict__ W1v,
                               const float* __restrict__ b1v,
                               const float* __restrict__ W2v) {
  __shared__ float skey[RPE];
  __shared__ int sord[RPE];
  __shared__ float sbuf[RPE];
  int t = threadIdx.x;

  float w1 = W1v[t], bb = b1v[t];
  float key = (w1 != 0.f) ? (-bb / w1) : INFINITY;
  skey[t] = key;
  sord[t] = t;
  __syncthreads();

  for (int size = 2; size <= RPE; size <<= 1) {
    for (int stride = size >> 1; stride > 0; stride >>= 1) {
      int p = t ^ stride;
      if (p > t) {
        bool asc = ((t & size) == 0);
        float k1 = skey[t], k2 = skey[p];
        if ((k1 > k2) == asc) {
          skey[t] = k2;
          skey[p] = k1;
          int tmp = sord[t];
          sord[t] = sord[p];
          sord[p] = tmp;
        }
      }
      __syncthreads();
    }
  }
  g_tsort[t] = skey[t];
  int r = sord[t];
  float w1r = W1v[r], b1r = b1v[r];
  bool isPos = (w1r > 0.f), isNeg = (w1r < 0.f);
  bool isZero = (!isPos && !isNeg);
  float sgn = isPos ? 1.f : (isNeg ? -1.f : 0.f);

  for (int h = 0; h < HEADS; h++) {
    float w2 = W2v[r * HEADS + h];
    float cw = sgn * w1r * w2;
    float cb = sgn * b1r * w2;
    float f0c = isNeg ? (w1r * w2) : 0.f;
    float g0c = isNeg ? (b1r * w2)
                      : ((isZero && b1r > 0.f) ? (b1r * w2) : 0.f);

    __syncthreads();
    sbuf[t] = f0c;
    __syncthreads();
    for (int off = 256; off; off >>= 1) {
      if (t < off) sbuf[t] += sbuf[t + off];
      __syncthreads();
    }
    float F0 = sbuf[0];
    __syncthreads();
    sbuf[t] = g0c;
    __syncthreads();
    for (int off = 256; off; off >>= 1) {
      if (t < off) sbuf[t] += sbuf[t + off];
      __syncthreads();
    }
    float G0 = sbuf[0];
    __syncthreads();
    sbuf[t] = cw;
    __syncthreads();
    for (int off = 1; off < RPE; off <<= 1) {
      float add = (t >= off) ? sbuf[t - off] : 0.f;
      __syncthreads();
      sbuf[t] += add;
      __syncthreads();
    }
    float inclW = sbuf[t];
    float totW = sbuf[RPE - 1];
    __syncthreads();
    sbuf[t] = cb;
    __syncthreads();
    for (int off = 1; off < RPE; off <<= 1) {
      float add = (t >= off) ? sbuf[t - off] : 0.f;
      __syncthreads();
      sbuf[t] += add;
      __syncthreads();
    }
    float inclB = sbuf[t];
    float totB = sbuf[RPE - 1];
    __syncthreads();

    g_F[h * (RPE + 1) + t] = F0 + (inclW - cw);
    g_G[h * (RPE + 1) + t] = G0 + (inclB - cb);
    if (t == RPE - 1) {
      g_F[h * (RPE + 1) + RPE] = F0 + totW;
      g_G[h * (RPE + 1) + RPE] = G0 + totB;
    }
  }
}

// ---------------- per-pair breakpoint index via binary search ------------
__global__ void __launch_bounds__(256) cpb_index(const float* __restrict__ am) {
  int i = blockIdx.x * 256 + threadIdx.x;
  if (i >= NQ * NK) return;
  float a = am[i];
  int lo = 0, hi = RPE;
  while (lo < hi) {
    int mid = (lo + hi) >> 1;
    if (g_tsort[mid] < a) lo = mid + 1;
    else hi = mid;
  }
  g_sidx[i] = (unsigned short)lo;
}

// ---------------- fused attention --------------------------------------
__global__ void __launch_bounds__(256) attention(
    const float* __restrict__ pad, const float* __restrict__ am) {
  __shared__ float sS[8][1028];
  __shared__ float sKV[64][36];
  __shared__ float sF[RPE + 1];
  __shared__ float sG[RPE + 1];

  int h = blockIdx.y;
  int q0 = blockIdx.x * 8;
  int t = threadIdx.x;
  int lane = t & 31;
  int qi = t >> 5;
  int q = q0 + qi;

  for (int i = t; i < RPE + 1; i += 256) {
    sF[i] = g_F[h * (RPE + 1) + i];
    sG[i] = g_G[h * (RPE + 1) + i];
  }

  float qreg[32];
  const float* qp = &g_q[q * DIM + h * HD];
#pragma unroll
  for (int d = 0; d < 32; d++) qreg[d] = qp[d] * SCALE;

  const float* amrow = &am[q * NK];
  const unsigned short* sxrow = &g_sidx[q * NK];
  float mymax = -INFINITY;

  for (int kt = 0; kt < 16; kt++) {
    int k0 = kt * 64;
    __syncthreads();
    {
      int idx = t * 2;
#pragma unroll
      for (int u = 0; u < 2; u++, idx++) {
        int r = idx >> 3, c4 = idx & 7;
        float4 v4 = *(const float4*)&g_k[(k0 + r) * DIM + h * HD + c4 * 4];
        sKV[r][c4 * 4 + 0] = v4.x;
        sKV[r][c4 * 4 + 1] = v4.y;
        sKV[r][c4 * 4 + 2] = v4.z;
        sKV[r][c4 * 4 + 3] = v4.w;
      }
    }
    __syncthreads();
#pragma unroll
    for (int u = 0; u < 2; u++) {
      int kl = lane + u * 32;
      int k = k0 + kl;
      float dot = 0.f;
#pragma unroll
      for (int d4 = 0; d4 < 8; d4++) {
        float4 kv = *(const float4*)&sKV[kl][d4 * 4];
        dot = fmaf(qreg[d4 * 4 + 0], kv.x, dot);
        dot = fmaf(qreg[d4 * 4 + 1], kv.y, dot);
        dot = fmaf(qreg[d4 * 4 + 2], kv.z, dot);
        dot = fmaf(qreg[d4 * 4 + 3], kv.w, dot);
      }
      float a = amrow[k];
      int idx2 = sxrow[k];
      float sv = dot + fmaf(a, sF[idx2], sG[idx2]) - 100.f * pad[k];
      sS[qi][k] = sv;
      mymax = fmaxf(mymax, sv);
    }
  }

#pragma unroll
  for (int off = 16; off; off >>= 1)
    mymax = fmaxf(mymax, __shfl_xor_sync(0xffffffffu, mymax, off));
  float mysum = 0.f;
  for (int kl = lane; kl < NK; kl += 32) {
    float e = __expf(sS[qi][kl] - mymax);
    sS[qi][kl] = e;
    mysum += e;
  }
#pragma unroll
  for (int off = 16; off; off >>= 1)
    mysum += __shfl_xor_sync(0xffffffffu, mysum, off);
  float inv = 1.f / mysum;

  float out = 0.f;
  for (int kt = 0; kt < 16; kt++) {
    int k0 = kt * 64;
    __syncthreads();
    {
      int idx = t * 2;
#pragma unroll
      for (int u = 0; u < 2; u++, idx++) {
        int r = idx >> 3, c4 = idx & 7;
        float4 v4 = *(const float4*)&g_v[(k0 + r) * DIM + h * HD + c4 * 4];
        sKV[r][c4 * 4 + 0] = v4.x;
        sKV[r][c4 * 4 + 1] = v4.y;
        sKV[r][c4 * 4 + 2] = v4.z;
        sKV[r][c4 * 4 + 3] = v4.w;
      }
    }
    __syncthreads();
#pragma unroll
    for (int kl = 0; kl < 64; kl++) {
      out = fmaf(sS[qi][k0 + kl], sKV[kl][lane], out);
    }
  }
  g_x[q * DIM + h * HD + lane] = out * inv;
}

// ---------------- launch ------------------------------------------------
extern "C" void kernel_launch(void* const* d_in, const int* in_sizes, int n_in,
                              void* d_out, int out_size) {
  const float* query = (const float*)d_in[0];
  const float* kin   = (const float*)d_in[1];
  const float* vin   = (const float*)d_in[2];
  const float* pad   = (const float*)d_in[3];
  const float* am    = (const float*)d_in[4];
  const float* Wq    = (const float*)d_in[5];
  const float* bq    = (const float*)d_in[6];
  const float* Wk    = (const float*)d_in[7];
  const float* bk    = (const float*)d_in[8];
  const float* Wv    = (const float*)d_in[9];
  const float* bv    = (const float*)d_in[10];
  const float* Wp    = (const float*)d_in[11];
  const float* bp    = (const float*)d_in[12];
  const float* W1    = (const float*)d_in[13];
  const float* b1    = (const float*)d_in[14];
  const float* W2    = (const float*)d_in[15];
  float* out = (float*)d_out;

  gemm256<<<dim3(NQ / 64, 4), 256>>>(query, Wq, bq, nullptr, 0);
  gemm256<<<dim3(NK / 64, 4), 256>>>(kin, Wk, bk, nullptr, 1);
  gemm256<<<dim3(NK / 64, 4), 256>>>(vin, Wv, bv, nullptr, 2);
  cpb_precompute<<<1, RPE>>>(W1, b1, W2);
  cpb_index<<<(NQ * NK) / 256, 256>>>(am);
  attention<<<dim3(NQ / 8, HEADS), 256>>>(pad, am);
  gemm256<<<dim3(NQ / 64, 4), 256>>>(nullptr, Wp, bp, out, 3);
}

// round 2
// speedup vs baseline: 1.6662x; 1.6662x over previous
#include <cuda_runtime.h>
#include <math.h>

#define NQ 512
#define NK 1024
#define DIM 256
#define HEADS 8
#define HD 32
#define RPE 512
#define SCALE 0.17677669529663687f
#define FULLMASK 0xffffffffu

// ---------------- scratch (device globals; no allocation) ----------------
__device__ float g_q[NQ * DIM];
__device__ float g_k[NK * DIM];
__device__ float g_v[NK * DIM];
__device__ float g_x[NQ * DIM];
__device__ float g_tsort[RPE];
__device__ float g_F[HEADS * (RPE + 1)];
__device__ float g_G[HEADS * (RPE + 1)];
__device__ unsigned short g_sidx[NQ * NK];

// ---------------- combined QKV projection GEMM (64x64 tiles) -------------
__global__ void __launch_bounds__(256) gemm_qkv(
    const float* __restrict__ query, const float* __restrict__ kin,
    const float* __restrict__ vin,
    const float* __restrict__ Wq, const float* __restrict__ bq,
    const float* __restrict__ Wk, const float* __restrict__ bk,
    const float* __restrict__ Wv, const float* __restrict__ bv) {
  __shared__ float As[16][64];
  __shared__ float Bs[16][64];
  int sel = blockIdx.z;
  const float* A = (sel == 0) ? query : (sel == 1) ? kin : vin;
  const float* W = (sel == 0) ? Wq : (sel == 1) ? Wk : Wv;
  const float* bias = (sel == 0) ? bq : (sel == 1) ? bk : bv;
  float* C = (sel == 0) ? g_q : (sel == 1) ? g_k : g_v;
  int M = (sel == 0) ? NQ : NK;

  int bm = blockIdx.x * 64, bn = blockIdx.y * 64;
  if (bm >= M) return;

  int tid = threadIdx.x;
  int tx = tid % 16, ty = tid / 16;
  float acc[4][4] = {};

  for (int k0 = 0; k0 < 256; k0 += 16) {
    {
      int r = tid >> 2, c4 = tid & 3;
      float4 av = *(const float4*)&A[(bm + r) * 256 + k0 + c4 * 4];
      As[c4 * 4 + 0][r] = av.x;
      As[c4 * 4 + 1][r] = av.y;
      As[c4 * 4 + 2][r] = av.z;
      As[c4 * 4 + 3][r] = av.w;
    }
    {
      int r = tid >> 4, c4 = tid & 15;
      *(float4*)&Bs[r][c4 * 4] = *(const float4*)&W[(k0 + r) * 256 + bn + c4 * 4];
    }
    __syncthreads();
#pragma unroll
    for (int k = 0; k < 16; k++) {
      float a[4], b[4];
#pragma unroll
      for (int i = 0; i < 4; i++) a[i] = As[k][ty * 4 + i];
#pragma unroll
      for (int j = 0; j < 4; j++) b[j] = Bs[k][tx * 4 + j];
#pragma unroll
      for (int i = 0; i < 4; i++)
#pragma unroll
        for (int j = 0; j < 4; j++) acc[i][j] = fmaf(a[i], b[j], acc[i][j]);
    }
    __syncthreads();
  }
#pragma unroll
  for (int i = 0; i < 4; i++) {
    int row = bm + ty * 4 + i;
#pragma unroll
    for (int j = 0; j < 4; j++) {
      int col = bn + tx * 4 + j;
      C[row * 256 + col] = acc[i][j] + bias[col];
    }
  }
}

// ---------------- output projection GEMM (32x64 tiles, A = g_x) ----------
__global__ void __launch_bounds__(256) gemm_out(
    const float* __restrict__ W, const float* __restrict__ bias,
    float* __restrict__ C) {
  __shared__ float As[16][32];
  __shared__ float Bs[16][64];
  const float* A = g_x;
  int bm = blockIdx.x * 32, bn = blockIdx.y * 64;
  int tid = threadIdx.x;
  int tx = tid % 16, ty = tid / 16;  // ty: 2 rows each, tx: 4 cols each
  float acc[2][4] = {};

  for (int k0 = 0; k0 < 256; k0 += 16) {
    if (tid < 128) {
      int r = tid >> 2, c4 = tid & 3;  // r 0..31, c4 0..3
      float4 av = *(const float4*)&A[(bm + r) * 256 + k0 + c4 * 4];
      As[c4 * 4 + 0][r] = av.x;
      As[c4 * 4 + 1][r] = av.y;
      As[c4 * 4 + 2][r] = av.z;
      As[c4 * 4 + 3][r] = av.w;
    }
    {
      int r = tid >> 4, c4 = tid & 15;
      *(float4*)&Bs[r][c4 * 4] = *(const float4*)&W[(k0 + r) * 256 + bn + c4 * 4];
    }
    __syncthreads();
#pragma unroll
    for (int k = 0; k < 16; k++) {
      float a[2], b[4];
#pragma unroll
      for (int i = 0; i < 2; i++) a[i] = As[k][ty * 2 + i];
#pragma unroll
      for (int j = 0; j < 4; j++) b[j] = Bs[k][tx * 4 + j];
#pragma unroll
      for (int i = 0; i < 2; i++)
#pragma unroll
        for (int j = 0; j < 4; j++) acc[i][j] = fmaf(a[i], b[j], acc[i][j]);
    }
    __syncthreads();
  }
#pragma unroll
  for (int i = 0; i < 2; i++) {
    int row = bm + ty * 2 + i;
#pragma unroll
    for (int j = 0; j < 4; j++) {
      int col = bn + tx * 4 + j;
      C[row * 256 + col] = acc[i][j] + bias[col];
    }
  }
}

// ---------------- CPB precompute: sort + shfl-based vector scans ---------
// bias_h(a) = a*F_h[idx] + G_h[idx], idx = #{p : t_sorted[p] < a}
__global__ void __launch_bounds__(512) cpb_precompute(
    const float* __restrict__ W1v, const float* __restrict__ b1v,
    const float* __restrict__ W2v) {
  __shared__ float skey[RPE];
  __shared__ int sord[RPE];
  __shared__ float swtA[16][8];
  __shared__ float swtB[16][8];
  __shared__ float sF0[8], sG0[8];
  __shared__ float sTotW[8], sTotB[8];
  int t = threadIdx.x, lane = t & 31, warp = t >> 5;

  float w1 = W1v[t], bb = b1v[t];
  skey[t] = (w1 != 0.f) ? (-bb / w1) : INFINITY;
  sord[t] = t;
  __syncthreads();

  for (int size = 2; size <= RPE; size <<= 1) {
    for (int stride = size >> 1; stride > 0; stride >>= 1) {
      int p = t ^ stride;
      if (p > t) {
        bool asc = ((t & size) == 0);
        float k1 = skey[t], k2 = skey[p];
        if ((k1 > k2) == asc) {
          skey[t] = k2;
          skey[p] = k1;
          int tmp = sord[t];
          sord[t] = sord[p];
          sord[p] = tmp;
        }
      }
      __syncthreads();
    }
  }
  g_tsort[t] = skey[t];
  int r = sord[t];
  float w1r = W1v[r], b1r = b1v[r];
  bool isPos = (w1r > 0.f), isNeg = (w1r < 0.f);
  bool isZero = (!isPos && !isNeg);
  float sgn = isPos ? 1.f : (isNeg ? -1.f : 0.f);

  float ocw[8], ocb[8], cw[8], cb[8], f0[8], g0[8];
#pragma unroll
  for (int h = 0; h < 8; h++) {
    float w2 = W2v[r * HEADS + h];
    ocw[h] = sgn * w1r * w2;
    ocb[h] = sgn * b1r * w2;
    cw[h] = ocw[h];
    cb[h] = ocb[h];
    f0[h] = isNeg ? (w1r * w2) : 0.f;
    g0[h] = isNeg ? (b1r * w2) : ((isZero && b1r > 0.f) ? (b1r * w2) : 0.f);
  }

  // block reduce f0, g0 (totals at a = -inf)
#pragma unroll
  for (int o = 16; o; o >>= 1)
#pragma unroll
    for (int h = 0; h < 8; h++) {
      f0[h] += __shfl_xor_sync(FULLMASK, f0[h], o);
      g0[h] += __shfl_xor_sync(FULLMASK, g0[h], o);
    }
  if (lane == 0)
#pragma unroll
    for (int h = 0; h < 8; h++) {
      swtA[warp][h] = f0[h];
      swtB[warp][h] = g0[h];
    }
  __syncthreads();
  if (t < 8) {
    float sa = 0.f, sb = 0.f;
    for (int ww = 0; ww < 16; ww++) {
      sa += swtA[ww][t];
      sb += swtB[ww][t];
    }
    sF0[t] = sa;
    sG0[t] = sb;
  }
  __syncthreads();

  // warp inclusive scans of cw, cb
#pragma unroll
  for (int o = 1; o < 32; o <<= 1) {
#pragma unroll
    for (int h = 0; h < 8; h++) {
      float ta = __shfl_up_sync(FULLMASK, cw[h], o);
      float tb = __shfl_up_sync(FULLMASK, cb[h], o);
      if (lane >= o) {
        cw[h] += ta;
        cb[h] += tb;
      }
    }
  }
  if (lane == 31)
#pragma unroll
    for (int h = 0; h < 8; h++) {
      swtA[warp][h] = cw[h];
      swtB[warp][h] = cb[h];
    }
  __syncthreads();

  // warp 0: scan the 16 warp-totals, write back EXCLUSIVE offsets
  if (warp == 0) {
    float va[8], vb[8], owa[8], owb[8];
#pragma unroll
    for (int h = 0; h < 8; h++) {
      owa[h] = (lane < 16) ? swtA[lane][h] : 0.f;
      owb[h] = (lane < 16) ? swtB[lane][h] : 0.f;
      va[h] = owa[h];
      vb[h] = owb[h];
    }
#pragma unroll
    for (int o = 1; o < 16; o <<= 1)
#pragma unroll
      for (int h = 0; h < 8; h++) {
        float ta = __shfl_up_sync(FULLMASK, va[h], o);
        float tb = __shfl_up_sync(FULLMASK, vb[h], o);
        if (lane >= o) {
          va[h] += ta;
          vb[h] += tb;
        }
      }
    if (lane < 16) {
#pragma unroll
      for (int h = 0; h < 8; h++) {
        swtA[lane][h] = va[h] - owa[h];
        swtB[lane][h] = vb[h] - owb[h];
        if (lane == 15) {
          sTotW[h] = va[h];
          sTotB[h] = vb[h];
        }
      }
    }
  }
  __syncthreads();

#pragma unroll
  for (int h = 0; h < 8; h++) {
    float excl = (cw[h] - ocw[h]) + swtA[warp][h];
    float exclb = (cb[h] - ocb[h]) + swtB[warp][h];
    g_F[h * (RPE + 1) + t] = sF0[h] + excl;
    g_G[h * (RPE + 1) + t] = sG0[h] + exclb;
  }
  if (t == 0)
#pragma unroll
    for (int h = 0; h < 8; h++) {
      g_F[h * (RPE + 1) + RPE] = sF0[h] + sTotW[h];
      g_G[h * (RPE + 1) + RPE] = sG0[h] + sTotB[h];
    }
}

// ---------------- per-pair breakpoint index via binary search ------------
__global__ void __launch_bounds__(256) cpb_index(const float* __restrict__ am) {
  int i = blockIdx.x * 256 + threadIdx.x;
  float a = __ldg(&am[i]);
  int lo = 0, hi = RPE;
  while (lo < hi) {
    int mid = (lo + hi) >> 1;
    if (g_tsort[mid] < a) lo = mid + 1;
    else hi = mid;
  }
  g_sidx[i] = (unsigned short)lo;
}

// ---------------- fused attention (lane-per-key, 8 queries/block) --------
struct AttnSmem {
  float sQ[8][32];
  float sKV[256][36];
  float sP[1024][8];
  float sF[RPE + 1];
  float sG[RPE + 1];
  float sRed[8][8];
  float sOut[8][8][32];
};

__global__ void __launch_bounds__(256) attention(const float* __restrict__ pad,
                                                 const float* __restrict__ am) {
  extern __shared__ char smem_raw[];
  AttnSmem* S = (AttnSmem*)smem_raw;
  const int h = blockIdx.y;
  const int q0 = blockIdx.x * 8;
  const int t = threadIdx.x;
  const int lane = t & 31, w = t >> 5;

  // load Q tile (scaled) and CPB tables
  S->sQ[w][lane] = g_q[(q0 + w) * DIM + h * HD + lane] * SCALE;
  for (int i = t; i <= RPE; i += 256) {
    S->sF[i] = g_F[h * (RPE + 1) + i];
    S->sG[i] = g_G[h * (RPE + 1) + i];
  }

  float sv[4][8];
  float rmax[8];
#pragma unroll
  for (int qi = 0; qi < 8; qi++) rmax[qi] = -INFINITY;

  const int klocal = w * 32 + lane;

  // ---- QK + bias + padding: lane owns one key per 256-key tile ----
#pragma unroll
  for (int tl = 0; tl < 4; tl++) {
    __syncthreads();
#pragma unroll
    for (int i = 0; i < 8; i++) {
      int j = t + i * 256;
      int rr = j >> 3, c = j & 7;
      *(float4*)&S->sKV[rr][c * 4] =
          *(const float4*)&g_k[(tl * 256 + rr) * DIM + h * HD + c * 4];
    }
    __syncthreads();
    int kglob = tl * 256 + klocal;
    float acc[8];
#pragma unroll
    for (int qi = 0; qi < 8; qi++) acc[qi] = 0.f;
#pragma unroll
    for (int c = 0; c < 8; c++) {
      float4 kv = *(const float4*)&S->sKV[klocal][c * 4];
#pragma unroll
      for (int qi = 0; qi < 8; qi++) {
        float4 qv = *(const float4*)&S->sQ[qi][c * 4];
        acc[qi] = fmaf(qv.x, kv.x, acc[qi]);
        acc[qi] = fmaf(qv.y, kv.y, acc[qi]);
        acc[qi] = fmaf(qv.z, kv.z, acc[qi]);
        acc[qi] = fmaf(qv.w, kv.w, acc[qi]);
      }
    }
    float padv = __ldg(&pad[kglob]) * 100.f;
#pragma unroll
    for (int qi = 0; qi < 8; qi++) {
      float a = __ldg(&am[(q0 + qi) * NK + kglob]);
      int ix = g_sidx[(q0 + qi) * NK + kglob];
      float v = acc[qi] + fmaf(a, S->sF[ix], S->sG[ix]) - padv;
      sv[tl][qi] = v;
      rmax[qi] = fmaxf(rmax[qi], v);
    }
  }

  // ---- row max: warp shfl + cross-warp smem ----
#pragma unroll
  for (int o = 16; o; o >>= 1)
#pragma unroll
    for (int qi = 0; qi < 8; qi++)
      rmax[qi] = fmaxf(rmax[qi], __shfl_xor_sync(FULLMASK, rmax[qi], o));
  if (lane == 0)
#pragma unroll
    for (int qi = 0; qi < 8; qi++) S->sRed[w][qi] = rmax[qi];
  __syncthreads();
#pragma unroll
  for (int qi = 0; qi < 8; qi++) {
    float m = -INFINITY;
#pragma unroll
    for (int ww = 0; ww < 8; ww++) m = fmaxf(m, S->sRed[ww][qi]);
    rmax[qi] = m;
  }
  __syncthreads();  // sRed reuse guard

  // ---- exp + write probs + row sum ----
  float rsum[8];
#pragma unroll
  for (int qi = 0; qi < 8; qi++) rsum[qi] = 0.f;
#pragma unroll
  for (int tl = 0; tl < 4; tl++) {
    int kk = tl * 256 + klocal;
    float e[8];
#pragma unroll
    for (int qi = 0; qi < 8; qi++) {
      e[qi] = __expf(sv[tl][qi] - rmax[qi]);
      rsum[qi] += e[qi];
    }
    *(float4*)&S->sP[kk][0] = make_float4(e[0], e[1], e[2], e[3]);
    *(float4*)&S->sP[kk][4] = make_float4(e[4], e[5], e[6], e[7]);
  }
#pragma unroll
  for (int o = 16; o; o >>= 1)
#pragma unroll
    for (int qi = 0; qi < 8; qi++)
      rsum[qi] += __shfl_xor_sync(FULLMASK, rsum[qi], o);
  if (lane == 0)
#pragma unroll
    for (int qi = 0; qi < 8; qi++) S->sRed[w][qi] = rsum[qi];
  __syncthreads();
  float inv[8];
#pragma unroll
  for (int qi = 0; qi < 8; qi++) {
    float s = 0.f;
#pragma unroll
    for (int ww = 0; ww < 8; ww++) s += S->sRed[ww][qi];
    inv[qi] = 1.f / s;
  }

  // ---- AV: lane owns one output dim; warp owns 32 keys per tile ----
  float out[8];
#pragma unroll
  for (int qi = 0; qi < 8; qi++) out[qi] = 0.f;
#pragma unroll
  for (int tl = 0; tl < 4; tl++) {
    __syncthreads();
#pragma unroll
    for (int i = 0; i < 8; i++) {
      int j = t + i * 256;
      int rr = j >> 3, c = j & 7;
      *(float4*)&S->sKV[rr][c * 4] =
          *(const float4*)&g_v[(tl * 256 + rr) * DIM + h * HD + c * 4];
    }
    __syncthreads();
#pragma unroll
    for (int jj = 0; jj < 32; jj++) {
      int kl = w * 32 + jj;
      int kk = tl * 256 + kl;
      float vv = S->sKV[kl][lane];
      float4 p0 = *(const float4*)&S->sP[kk][0];
      float4 p1 = *(const float4*)&S->sP[kk][4];
      out[0] = fmaf(p0.x, vv, out[0]);
      out[1] = fmaf(p0.y, vv, out[1]);
      out[2] = fmaf(p0.z, vv, out[2]);
      out[3] = fmaf(p0.w, vv, out[3]);
      out[4] = fmaf(p1.x, vv, out[4]);
      out[5] = fmaf(p1.y, vv, out[5]);
      out[6] = fmaf(p1.z, vv, out[6]);
      out[7] = fmaf(p1.w, vv, out[7]);
    }
  }
#pragma unroll
  for (int qi = 0; qi < 8; qi++) S->sOut[w][qi][lane] = out[qi] * inv[qi];
  __syncthreads();
  {
    float accf = 0.f;
#pragma unroll
    for (int ww = 0; ww < 8; ww++) accf += S->sOut[ww][w][lane];
    g_x[(q0 + w) * DIM + h * HD + lane] = accf;
  }
}

// ---------------- launch ------------------------------------------------
extern "C" void kernel_launch(void* const* d_in, const int* in_sizes, int n_in,
                              void* d_out, int out_size) {
  const float* query = (const float*)d_in[0];
  const float* kin   = (const float*)d_in[1];
  const float* vin   = (const float*)d_in[2];
  const float* pad   = (const float*)d_in[3];
  const float* am    = (const float*)d_in[4];
  const float* Wq    = (const float*)d_in[5];
  const float* bq    = (const float*)d_in[6];
  const float* Wk    = (const float*)d_in[7];
  const float* bk    = (const float*)d_in[8];
  const float* Wv    = (const float*)d_in[9];
  const float* bv    = (const float*)d_in[10];
  const float* Wp    = (const float*)d_in[11];
  const float* bp    = (const float*)d_in[12];
  const float* W1    = (const float*)d_in[13];
  const float* b1    = (const float*)d_in[14];
  const float* W2    = (const float*)d_in[15];
  float* out = (float*)d_out;

  cudaFuncSetAttribute(attention, cudaFuncAttributeMaxDynamicSharedMemorySize,
                       (int)sizeof(AttnSmem));

  gemm_qkv<<<dim3(16, 4, 3), 256>>>(query, kin, vin, Wq, bq, Wk, bk, Wv, bv);
  cpb_precompute<<<1, RPE>>>(W1, b1, W2);
  cpb_index<<<(NQ * NK) / 256, 256>>>(am);
  attention<<<dim3(NQ / 8, HEADS), 256, sizeof(AttnSmem)>>>(pad, am);
  gemm_out<<<dim3(NQ / 32, 4), 256>>>(Wp, bp, out);
}

// round 4
// speedup vs baseline: 1.7901x; 1.0744x over previous
#include <cuda_runtime.h>
#include <math.h>

#define NQ 512
#define NK 1024
#define DIM 256
#define HEADS 8
#define HD 32
#define RPE 512
#define SCALE 0.17677669529663687f
#define FULLMASK 0xffffffffu

// ---------------- scratch (device globals; no allocation) ----------------
__device__ float g_q[NQ * DIM];
__device__ float g_k[NK * DIM];
__device__ float g_v[NK * DIM];
__device__ float g_x[NQ * DIM];
__device__ float g_tsort[RPE];
__device__ float g_F[HEADS * (RPE + 1)];
__device__ float g_G[HEADS * (RPE + 1)];
__device__ unsigned short g_sidx[NQ * NK];

// ---------------- GEMM 32x64 tiles, 128 threads, 4x4 per thread ----------
// sel: 0 -> q proj, 1 -> k proj, 2 -> v proj, 3 -> out proj (A = g_x)
__global__ void __launch_bounds__(128) gemm32(
    const float* __restrict__ query, const float* __restrict__ kin,
    const float* __restrict__ vin,
    const float* __restrict__ Wq, const float* __restrict__ bq,
    const float* __restrict__ Wk, const float* __restrict__ bk,
    const float* __restrict__ Wv, const float* __restrict__ bv,
    const float* __restrict__ Wp, const float* __restrict__ bp,
    float* __restrict__ outp, int selBase) {
  __shared__ float As[16][33];
  __shared__ float Bs[16][64];

  int sel = blockIdx.z + selBase;
  const float* A;
  const float* W;
  const float* bias;
  float* C;
  int M;
  if (sel == 0) { A = query; W = Wq; bias = bq; C = g_q; M = NQ; }
  else if (sel == 1) { A = kin; W = Wk; bias = bk; C = g_k; M = NK; }
  else if (sel == 2) { A = vin; W = Wv; bias = bv; C = g_v; M = NK; }
  else { A = g_x; W = Wp; bias = bp; C = outp; M = NQ; }

  int bm = blockIdx.x * 32;
  if (bm >= M) return;
  int bn = blockIdx.y * 64;

  int t = threadIdx.x;
  int tx = t % 16, ty = t / 16;
  float acc[4][4] = {};

  for (int k0 = 0; k0 < 256; k0 += 16) {
    {  // A tile: 32 rows x 16 k (transposed into As)
      int r = t >> 2, c4 = t & 3;
      float4 av = *(const float4*)&A[(bm + r) * 256 + k0 + c4 * 4];
      As[c4 * 4 + 0][r] = av.x;
      As[c4 * 4 + 1][r] = av.y;
      As[c4 * 4 + 2][r] = av.z;
      As[c4 * 4 + 3][r] = av.w;
    }
    {  // W tile: 16 k x 64 cols
#pragma unroll
      for (int u = 0; u < 2; u++) {
        int idx = t * 2 + u;
        int r = idx >> 4, c4 = idx & 15;
        *(float4*)&Bs[r][c4 * 4] = *(const float4*)&W[(k0 + r) * 256 + bn + c4 * 4];
      }
    }
    __syncthreads();
#pragma unroll
    for (int k = 0; k < 16; k++) {
      float a[4], b[4];
#pragma unroll
      for (int i = 0; i < 4; i++) a[i] = As[k][ty * 4 + i];
#pragma unroll
      for (int j = 0; j < 4; j++) b[j] = Bs[k][tx * 4 + j];
#pragma unroll
      for (int i = 0; i < 4; i++)
#pragma unroll
        for (int j = 0; j < 4; j++) acc[i][j] = fmaf(a[i], b[j], acc[i][j]);
    }
    __syncthreads();
  }
#pragma unroll
  for (int i = 0; i < 4; i++) {
    int row = bm + ty * 4 + i;
#pragma unroll
    for (int j = 0; j < 4; j++) {
      int col = bn + tx * 4 + j;
      C[row * 256 + col] = acc[i][j] + bias[col];
    }
  }
}

// ---------------- CPB precompute: sort + shfl-based vector scans ---------
// bias_h(a) = a*F_h[idx] + G_h[idx], idx = #{p : t_sorted[p] < a}
__global__ void __launch_bounds__(512) cpb_precompute(
    const float* __restrict__ W1v, const float* __restrict__ b1v,
    const float* __restrict__ W2v) {
  __shared__ float skey[RPE];
  __shared__ int sord[RPE];
  __shared__ float swtA[16][8];
  __shared__ float swtB[16][8];
  __shared__ float sF0[8], sG0[8];
  __shared__ float sTotW[8], sTotB[8];
  int t = threadIdx.x, lane = t & 31, warp = t >> 5;

  float w1 = W1v[t], bb = b1v[t];
  skey[t] = (w1 != 0.f) ? (-bb / w1) : INFINITY;
  sord[t] = t;
  __syncthreads();

  for (int size = 2; size <= RPE; size <<= 1) {
    for (int stride = size >> 1; stride > 0; stride >>= 1) {
      int p = t ^ stride;
      if (p > t) {
        bool asc = ((t & size) == 0);
        float k1 = skey[t], k2 = skey[p];
        if ((k1 > k2) == asc) {
          skey[t] = k2;
          skey[p] = k1;
          int tmp = sord[t];
          sord[t] = sord[p];
          sord[p] = tmp;
        }
      }
      __syncthreads();
    }
  }
  g_tsort[t] = skey[t];
  int r = sord[t];
  float w1r = W1v[r], b1r = b1v[r];
  bool isPos = (w1r > 0.f), isNeg = (w1r < 0.f);
  bool isZero = (!isPos && !isNeg);
  float sgn = isPos ? 1.f : (isNeg ? -1.f : 0.f);

  float ocw[8], ocb[8], cw[8], cb[8], f0[8], g0[8];
#pragma unroll
  for (int h = 0; h < 8; h++) {
    float w2 = W2v[r * HEADS + h];
    ocw[h] = sgn * w1r * w2;
    ocb[h] = sgn * b1r * w2;
    cw[h] = ocw[h];
    cb[h] = ocb[h];
    f0[h] = isNeg ? (w1r * w2) : 0.f;
    g0[h] = isNeg ? (b1r * w2) : ((isZero && b1r > 0.f) ? (b1r * w2) : 0.f);
  }

#pragma unroll
  for (int o = 16; o; o >>= 1)
#pragma unroll
    for (int h = 0; h < 8; h++) {
      f0[h] += __shfl_xor_sync(FULLMASK, f0[h], o);
      g0[h] += __shfl_xor_sync(FULLMASK, g0[h], o);
    }
  if (lane == 0)
#pragma unroll
    for (int h = 0; h < 8; h++) {
      swtA[warp][h] = f0[h];
      swtB[warp][h] = g0[h];
    }
  __syncthreads();
  if (t < 8) {
    float sa = 0.f, sb = 0.f;
    for (int ww = 0; ww < 16; ww++) {
      sa += swtA[ww][t];
      sb += swtB[ww][t];
    }
    sF0[t] = sa;
    sG0[t] = sb;
  }
  __syncthreads();

#pragma unroll
  for (int o = 1; o < 32; o <<= 1) {
#pragma unroll
    for (int h = 0; h < 8; h++) {
      float ta = __shfl_up_sync(FULLMASK, cw[h], o);
      float tb = __shfl_up_sync(FULLMASK, cb[h], o);
      if (lane >= o) {
        cw[h] += ta;
        cb[h] += tb;
      }
    }
  }
  if (lane == 31)
#pragma unroll
    for (int h = 0; h < 8; h++) {
      swtA[warp][h] = cw[h];
      swtB[warp][h] = cb[h];
    }
  __syncthreads();

  if (warp == 0) {
    float va[8], vb[8], owa[8], owb[8];
#pragma unroll
    for (int h = 0; h < 8; h++) {
      owa[h] = (lane < 16) ? swtA[lane][h] : 0.f;
      owb[h] = (lane < 16) ? swtB[lane][h] : 0.f;
      va[h] = owa[h];
      vb[h] = owb[h];
    }
#pragma unroll
    for (int o = 1; o < 16; o <<= 1)
#pragma unroll
      for (int h = 0; h < 8; h++) {
        float ta = __shfl_up_sync(FULLMASK, va[h], o);
        float tb = __shfl_up_sync(FULLMASK, vb[h], o);
        if (lane >= o) {
          va[h] += ta;
          vb[h] += tb;
        }
      }
    if (lane < 16) {
#pragma unroll
      for (int h = 0; h < 8; h++) {
        swtA[lane][h] = va[h] - owa[h];
        swtB[lane][h] = vb[h] - owb[h];
        if (lane == 15) {
          sTotW[h] = va[h];
          sTotB[h] = vb[h];
        }
      }
    }
  }
  __syncthreads();

#pragma unroll
  for (int h = 0; h < 8; h++) {
    float excl = (cw[h] - ocw[h]) + swtA[warp][h];
    float exclb = (cb[h] - ocb[h]) + swtB[warp][h];
    g_F[h * (RPE + 1) + t] = sF0[h] + excl;
    g_G[h * (RPE + 1) + t] = sG0[h] + exclb;
  }
  if (t == 0)
#pragma unroll
    for (int h = 0; h < 8; h++) {
      g_F[h * (RPE + 1) + RPE] = sF0[h] + sTotW[h];
      g_G[h * (RPE + 1) + RPE] = sG0[h] + sTotB[h];
    }
}

// ---------------- per-pair breakpoint index (branchless, x4) -------------
__global__ void __launch_bounds__(256) cpb_index(const float* __restrict__ am) {
  __shared__ float st[RPE];
  int t = threadIdx.x;
  for (int i = t; i < RPE; i += 256) st[i] = g_tsort[i];
  __syncthreads();
  int base = (blockIdx.x * 256 + t) * 4;
  float4 a4 = *(const float4*)&am[base];
  float av[4] = {a4.x, a4.y, a4.z, a4.w};
  unsigned short res[4];
#pragma unroll
  for (int u = 0; u < 4; u++) {
    int pos = 0;
#pragma unroll
    for (int sgm = 256; sgm >= 1; sgm >>= 1)
      if (st[pos + sgm - 1] < av[u]) pos += sgm;
    res[u] = (unsigned short)pos;
  }
  *(ushort4*)&g_sidx[base] = make_ushort4(res[0], res[1], res[2], res[3]);
}

// ---------------- fused attention: online softmax, 8 q x 1 head ----------
// NOTE member order: all float4-accessed members (sQ, sK, sPt, sRed) sit at
// 16B-aligned offsets BEFORE the odd-sized sF/sG tables (513 floats = 2052 B).
struct AttnSmem {
  float sQ[8][32];         // @0      scaled Q tile
  float sK[256][36];       // @1024   K tile staging (conflict-free pad)
  float sPt[256][12];      // @37888  per-tile probs (16B-aligned rows)
  float sRed[8][8];        // @50176  [qi][warp] partial max/sum (float4 reads)
  float sF[RPE + 4];       // @50432
  float sG[RPE + 4];
};
// sOut (8KB) aliases sK after the last tile.

__global__ void __launch_bounds__(256, 4) attention(
    const float* __restrict__ pad, const float* __restrict__ am) {
  extern __shared__ char raw[];
  AttnSmem* S = (AttnSmem*)raw;
  const int h = blockIdx.y;
  const int q0 = blockIdx.x * 8;
  const int t = threadIdx.x;
  const int lane = t & 31, w = t >> 5;

  S->sQ[w][lane] = g_q[(q0 + w) * DIM + h * HD + lane] * SCALE;
  for (int i = t; i <= RPE; i += 256) {
    S->sF[i] = g_F[h * (RPE + 1) + i];
    S->sG[i] = g_G[h * (RPE + 1) + i];
  }

  float out[8], m[8], s[8];
#pragma unroll
  for (int qi = 0; qi < 8; qi++) {
    out[qi] = 0.f;
    s[qi] = 0.f;
    m[qi] = -INFINITY;
  }

#pragma unroll 1
  for (int tl = 0; tl < 4; tl++) {
    __syncthreads();  // prev tile done reading sK / sRed
    // ---- stage K tile (256 keys x 32 dims) ----
#pragma unroll
    for (int i = 0; i < 8; i++) {
      int j = t + i * 256;
      int rr = j >> 3, c = j & 7;
      *(float4*)&S->sK[rr][c * 4] =
          *(const float4*)&g_k[(tl * 256 + rr) * DIM + h * HD + c * 4];
    }
    const int kglob = tl * 256 + t;
    float padv = 100.f * __ldg(&pad[kglob]);
    __syncthreads();

    // ---- dots: this thread's key vs 8 queries ----
    float acc[8];
#pragma unroll
    for (int qi = 0; qi < 8; qi++) acc[qi] = 0.f;
#pragma unroll
    for (int c = 0; c < 8; c++) {
      float4 kv = *(const float4*)&S->sK[t][c * 4];
#pragma unroll
      for (int qi = 0; qi < 8; qi++) {
        float4 qv = *(const float4*)&S->sQ[qi][c * 4];
        acc[qi] = fmaf(qv.x, kv.x, acc[qi]);
        acc[qi] = fmaf(qv.y, kv.y, acc[qi]);
        acc[qi] = fmaf(qv.z, kv.z, acc[qi]);
        acc[qi] = fmaf(qv.w, kv.w, acc[qi]);
      }
    }
    // ---- CPB bias + padding ----
#pragma unroll
    for (int qi = 0; qi < 8; qi++) {
      float a = __ldg(&am[(q0 + qi) * NK + kglob]);
      int ix = (int)g_sidx[(q0 + qi) * NK + kglob];
      acc[qi] += fmaf(a, S->sF[ix], S->sG[ix]) - padv;
    }

    // ---- block-wide tile max per query ----
    float tm[8];
#pragma unroll
    for (int qi = 0; qi < 8; qi++) tm[qi] = acc[qi];
#pragma unroll
    for (int o = 16; o; o >>= 1)
#pragma unroll
      for (int qi = 0; qi < 8; qi++)
        tm[qi] = fmaxf(tm[qi], __shfl_xor_sync(FULLMASK, tm[qi], o));
    if (lane == 0)
#pragma unroll
      for (int qi = 0; qi < 8; qi++) S->sRed[qi][w] = tm[qi];
    __syncthreads();

    // ---- online update: m, s, out rescale; probs in acc ----
#pragma unroll
    for (int qi = 0; qi < 8; qi++) {
      float4 r0 = *(const float4*)&S->sRed[qi][0];
      float4 r1 = *(const float4*)&S->sRed[qi][4];
      float mn = fmaxf(fmaxf(fmaxf(r0.x, r0.y), fmaxf(r0.z, r0.w)),
                       fmaxf(fmaxf(r1.x, r1.y), fmaxf(r1.z, r1.w)));
      mn = fmaxf(mn, m[qi]);
      float fq = __expf(m[qi] - mn);
      m[qi] = mn;
      float e = __expf(acc[qi] - mn);
      s[qi] = s[qi] * fq + e;
      out[qi] *= fq;
      acc[qi] = e;
    }
    // warp-private prob exchange
    *(float4*)&S->sPt[t][0] = make_float4(acc[0], acc[1], acc[2], acc[3]);
    *(float4*)&S->sPt[t][4] = make_float4(acc[4], acc[5], acc[6], acc[7]);
    __syncwarp();

    // ---- AV: warp covers its own 32 keys; V straight from L2 ----
    const float* vb = &g_v[(tl * 256 + w * 32) * DIM + h * HD + lane];
#pragma unroll
    for (int jj = 0; jj < 32; jj++) {
      float vv = __ldg(&vb[jj * DIM]);
      float4 p0 = *(const float4*)&S->sPt[w * 32 + jj][0];
      float4 p1 = *(const float4*)&S->sPt[w * 32 + jj][4];
      out[0] = fmaf(p0.x, vv, out[0]);
      out[1] = fmaf(p0.y, vv, out[1]);
      out[2] = fmaf(p0.z, vv, out[2]);
      out[3] = fmaf(p0.w, vv, out[3]);
      out[4] = fmaf(p1.x, vv, out[4]);
      out[5] = fmaf(p1.y, vv, out[5]);
      out[6] = fmaf(p1.z, vv, out[6]);
      out[7] = fmaf(p1.w, vv, out[7]);
    }
  }

  // ---- final sum reduce + normalize + cross-warp output reduce ----
  __syncthreads();  // all warps done with tile-3 sRed reads
#pragma unroll
  for (int o = 16; o; o >>= 1)
#pragma unroll
    for (int qi = 0; qi < 8; qi++)
      s[qi] += __shfl_xor_sync(FULLMASK, s[qi], o);
  if (lane == 0)
#pragma unroll
    for (int qi = 0; qi < 8; qi++) S->sRed[qi][w] = s[qi];
  __syncthreads();

  float (*sOut)[8][32] = (float(*)[8][32])S->sK;  // alias
#pragma unroll
  for (int qi = 0; qi < 8; qi++) {
    float4 r0 = *(const float4*)&S->sRed[qi][0];
    float4 r1 = *(const float4*)&S->sRed[qi][4];
    float stot = (r0.x + r0.y) + (r0.z + r0.w) + (r1.x + r1.y) + (r1.z + r1.w);
    sOut[w][qi][lane] = out[qi] * (1.f / stot);
  }
  __syncthreads();
  {
    float accf = 0.f;
#pragma unroll
    for (int ww = 0; ww < 8; ww++) accf += sOut[ww][w][lane];
    g_x[(q0 + w) * DIM + h * HD + lane] = accf;
  }
}

// ---------------- launch ------------------------------------------------
extern "C" void kernel_launch(void* const* d_in, const int* in_sizes, int n_in,
                              void* d_out, int out_size) {
  const float* query = (const float*)d_in[0];
  const float* kin   = (const float*)d_in[1];
  const float* vin   = (const float*)d_in[2];
  const float* pad   = (const float*)d_in[3];
  const float* am    = (const float*)d_in[4];
  const float* Wq    = (const float*)d_in[5];
  const float* bq    = (const float*)d_in[6];
  const float* Wk    = (const float*)d_in[7];
  const float* bk    = (const float*)d_in[8];
  const float* Wv    = (const float*)d_in[9];
  const float* bv    = (const float*)d_in[10];
  const float* Wp    = (const float*)d_in[11];
  const float* bp    = (const float*)d_in[12];
  const float* W1    = (const float*)d_in[13];
  const float* b1    = (const float*)d_in[14];
  const float* W2    = (const float*)d_in[15];
  float* out = (float*)d_out;

  cudaFuncSetAttribute(attention, cudaFuncAttributeMaxDynamicSharedMemorySize,
                       (int)sizeof(AttnSmem));

  // Q/K/V projections: 32x64 tiles (x covers NK/32; Q tiles guard out)
  gemm32<<<dim3(32, 4, 3), 128>>>(query, kin, vin, Wq, bq, Wk, bk, Wv, bv,
                                  Wp, bp, out, 0);
  cpb_precompute<<<1, RPE>>>(W1, b1, W2);
  cpb_index<<<NQ * NK / 4 / 256, 256>>>(am);
  attention<<<dim3(NQ / 8, HEADS), 256, sizeof(AttnSmem)>>>(pad, am);
  // output projection
  gemm32<<<dim3(16, 4, 1), 128>>>(query, kin, vin, Wq, bq, Wk, bk, Wv, bv,
                                  Wp, bp, out, 3);
}

// round 5
// speedup vs baseline: 1.8091x; 1.0106x over previous
#include <cuda_runtime.h>
#include <math.h>

#define NQ 512
#define NK 1024
#define DIM 256
#define HEADS 8
#define HD 32
#define RPE 512
#define SCALE 0.17677669529663687f
#define FULLMASK 0xffffffffu

// ---------------- packed fp32x2 helpers (Blackwell dual-FP32 pipe) -------
__device__ __forceinline__ unsigned long long pk2(float lo, float hi) {
  unsigned long long r;
  asm("mov.b64 %0, {%1, %2};" : "=l"(r) : "f"(lo), "f"(hi));
  return r;
}
__device__ __forceinline__ void upk2(float& lo, float& hi, unsigned long long v) {
  asm("mov.b64 {%0, %1}, %2;" : "=f"(lo), "=f"(hi) : "l"(v));
}
__device__ __forceinline__ void fma2(unsigned long long& d, unsigned long long a,
                                     unsigned long long b) {
  asm("fma.rn.f32x2 %0, %1, %2, %0;" : "+l"(d) : "l"(a), "l"(b));
}
__device__ __forceinline__ void mul2(unsigned long long& d, unsigned long long a) {
  asm("mul.rn.f32x2 %0, %0, %1;" : "+l"(d) : "l"(a));
}

// ---------------- scratch (device globals; no allocation) ----------------
__device__ float g_q[NQ * DIM];
__device__ float g_k[NK * DIM];
__device__ float g_v[NK * DIM];
__device__ float g_x[NQ * DIM];
__device__ float g_tsort[RPE];
__device__ float g_F[HEADS * (RPE + 1)];
__device__ float g_G[HEADS * (RPE + 1)];
__device__ unsigned short g_sidx[NQ * NK];

// ---------------- GEMM 32x64 tiles, 128 threads, 4x4/thread, f32x2 -------
// sel: 0 -> q proj, 1 -> k proj, 2 -> v proj, 3 -> out proj (A = g_x)
__global__ void __launch_bounds__(128) gemm32(
    const float* __restrict__ query, const float* __restrict__ kin,
    const float* __restrict__ vin,
    const float* __restrict__ Wq, const float* __restrict__ bq,
    const float* __restrict__ Wk, const float* __restrict__ bk,
    const float* __restrict__ Wv, const float* __restrict__ bv,
    const float* __restrict__ Wp, const float* __restrict__ bp,
    float* __restrict__ outp, int selBase) {
  __shared__ float As[16][36];  // 144B rows: float4-aligned
  __shared__ float Bs[16][64];

  int sel = blockIdx.z + selBase;
  const float* A;
  const float* W;
  const float* bias;
  float* C;
  int M;
  if (sel == 0) { A = query; W = Wq; bias = bq; C = g_q; M = NQ; }
  else if (sel == 1) { A = kin; W = Wk; bias = bk; C = g_k; M = NK; }
  else if (sel == 2) { A = vin; W = Wv; bias = bv; C = g_v; M = NK; }
  else { A = g_x; W = Wp; bias = bp; C = outp; M = NQ; }

  int bm = blockIdx.x * 32;
  if (bm >= M) return;
  int bn = blockIdx.y * 64;

  int t = threadIdx.x;
  int tx = t % 16, ty = t / 16;
  unsigned long long acc2[4][2];
#pragma unroll
  for (int i = 0; i < 4; i++) {
    acc2[i][0] = 0ull;
    acc2[i][1] = 0ull;
  }

  for (int k0 = 0; k0 < 256; k0 += 16) {
    {  // A tile: 32 rows x 16 k (transposed into As)
      int r = t >> 2, c4 = t & 3;
      float4 av = *(const float4*)&A[(bm + r) * 256 + k0 + c4 * 4];
      As[c4 * 4 + 0][r] = av.x;
      As[c4 * 4 + 1][r] = av.y;
      As[c4 * 4 + 2][r] = av.z;
      As[c4 * 4 + 3][r] = av.w;
    }
    {  // W tile: 16 k x 64 cols
#pragma unroll
      for (int u = 0; u < 2; u++) {
        int idx = t * 2 + u;
        int r = idx >> 4, c4 = idx & 15;
        *(float4*)&Bs[r][c4 * 4] = *(const float4*)&W[(k0 + r) * 256 + bn + c4 * 4];
      }
    }
    __syncthreads();
#pragma unroll
    for (int k = 0; k < 16; k++) {
      float4 a4 = *(const float4*)&As[k][ty * 4];
      ulonglong2 bp2 = *(const ulonglong2*)&Bs[k][tx * 4];
      unsigned long long ap[4];
      ap[0] = pk2(a4.x, a4.x);
      ap[1] = pk2(a4.y, a4.y);
      ap[2] = pk2(a4.z, a4.z);
      ap[3] = pk2(a4.w, a4.w);
#pragma unroll
      for (int i = 0; i < 4; i++) {
        fma2(acc2[i][0], ap[i], bp2.x);
        fma2(acc2[i][1], ap[i], bp2.y);
      }
    }
    __syncthreads();
  }
#pragma unroll
  for (int i = 0; i < 4; i++) {
    int row = bm + ty * 4 + i;
    int col = bn + tx * 4;
    float c0, c1, c2, c3;
    upk2(c0, c1, acc2[i][0]);
    upk2(c2, c3, acc2[i][1]);
    C[row * 256 + col + 0] = c0 + bias[col + 0];
    C[row * 256 + col + 1] = c1 + bias[col + 1];
    C[row * 256 + col + 2] = c2 + bias[col + 2];
    C[row * 256 + col + 3] = c3 + bias[col + 3];
  }
}

// ---------------- CPB precompute: sort + shfl-based vector scans ---------
// bias_h(a) = a*F_h[idx] + G_h[idx], idx = #{p : t_sorted[p] < a}
__global__ void __launch_bounds__(512) cpb_precompute(
    const float* __restrict__ W1v, const float* __restrict__ b1v,
    const float* __restrict__ W2v) {
  __shared__ float skey[RPE];
  __shared__ int sord[RPE];
  __shared__ float swtA[16][8];
  __shared__ float swtB[16][8];
  __shared__ float sF0[8], sG0[8];
  __shared__ float sTotW[8], sTotB[8];
  int t = threadIdx.x, lane = t & 31, warp = t >> 5;

  float w1 = W1v[t], bb = b1v[t];
  skey[t] = (w1 != 0.f) ? (-bb / w1) : INFINITY;
  sord[t] = t;
  __syncthreads();

  for (int size = 2; size <= RPE; size <<= 1) {
    for (int stride = size >> 1; stride > 0; stride >>= 1) {
      int p = t ^ stride;
      if (p > t) {
        bool asc = ((t & size) == 0);
        float k1 = skey[t], k2 = skey[p];
        if ((k1 > k2) == asc) {
          skey[t] = k2;
          skey[p] = k1;
          int tmp = sord[t];
          sord[t] = sord[p];
          sord[p] = tmp;
        }
      }
      __syncthreads();
    }
  }
  g_tsort[t] = skey[t];
  int r = sord[t];
  float w1r = W1v[r], b1r = b1v[r];
  bool isPos = (w1r > 0.f), isNeg = (w1r < 0.f);
  bool isZero = (!isPos && !isNeg);
  float sgn = isPos ? 1.f : (isNeg ? -1.f : 0.f);

  float ocw[8], ocb[8], cw[8], cb[8], f0[8], g0[8];
#pragma unroll
  for (int h = 0; h < 8; h++) {
    float w2 = W2v[r * HEADS + h];
    ocw[h] = sgn * w1r * w2;
    ocb[h] = sgn * b1r * w2;
    cw[h] = ocw[h];
    cb[h] = ocb[h];
    f0[h] = isNeg ? (w1r * w2) : 0.f;
    g0[h] = isNeg ? (b1r * w2) : ((isZero && b1r > 0.f) ? (b1r * w2) : 0.f);
  }

#pragma unroll
  for (int o = 16; o; o >>= 1)
#pragma unroll
    for (int h = 0; h < 8; h++) {
      f0[h] += __shfl_xor_sync(FULLMASK, f0[h], o);
      g0[h] += __shfl_xor_sync(FULLMASK, g0[h], o);
    }
  if (lane == 0)
#pragma unroll
    for (int h = 0; h < 8; h++) {
      swtA[warp][h] = f0[h];
      swtB[warp][h] = g0[h];
    }
  __syncthreads();
  if (t < 8) {
    float sa = 0.f, sb = 0.f;
    for (int ww = 0; ww < 16; ww++) {
      sa += swtA[ww][t];
      sb += swtB[ww][t];
    }
    sF0[t] = sa;
    sG0[t] = sb;
  }
  __syncthreads();

#pragma unroll
  for (int o = 1; o < 32; o <<= 1) {
#pragma unroll
    for (int h = 0; h < 8; h++) {
      float ta = __shfl_up_sync(FULLMASK, cw[h], o);
      float tb = __shfl_up_sync(FULLMASK, cb[h], o);
      if (lane >= o) {
        cw[h] += ta;
        cb[h] += tb;
      }
    }
  }
  if (lane == 31)
#pragma unroll
    for (int h = 0; h < 8; h++) {
      swtA[warp][h] = cw[h];
      swtB[warp][h] = cb[h];
    }
  __syncthreads();

  if (warp == 0) {
    float va[8], vb[8], owa[8], owb[8];
#pragma unroll
    for (int h = 0; h < 8; h++) {
      owa[h] = (lane < 16) ? swtA[lane][h] : 0.f;
      owb[h] = (lane < 16) ? swtB[lane][h] : 0.f;
      va[h] = owa[h];
      vb[h] = owb[h];
    }
#pragma unroll
    for (int o = 1; o < 16; o <<= 1)
#pragma unroll
      for (int h = 0; h < 8; h++) {
        float ta = __shfl_up_sync(FULLMASK, va[h], o);
        float tb = __shfl_up_sync(FULLMASK, vb[h], o);
        if (lane >= o) {
          va[h] += ta;
          vb[h] += tb;
        }
      }
    if (lane < 16) {
#pragma unroll
      for (int h = 0; h < 8; h++) {
        swtA[lane][h] = va[h] - owa[h];
        swtB[lane][h] = vb[h] - owb[h];
        if (lane == 15) {
          sTotW[h] = va[h];
          sTotB[h] = vb[h];
        }
      }
    }
  }
  __syncthreads();

#pragma unroll
  for (int h = 0; h < 8; h++) {
    float excl = (cw[h] - ocw[h]) + swtA[warp][h];
    float exclb = (cb[h] - ocb[h]) + swtB[warp][h];
    g_F[h * (RPE + 1) + t] = sF0[h] + excl;
    g_G[h * (RPE + 1) + t] = sG0[h] + exclb;
  }
  if (t == 0)
#pragma unroll
    for (int h = 0; h < 8; h++) {
      g_F[h * (RPE + 1) + RPE] = sF0[h] + sTotW[h];
      g_G[h * (RPE + 1) + RPE] = sG0[h] + sTotB[h];
    }
}

// ---------------- per-pair breakpoint index (branchless, x4) -------------
__global__ void __launch_bounds__(256) cpb_index(const float* __restrict__ am) {
  __shared__ float st[RPE];
  int t = threadIdx.x;
  for (int i = t; i < RPE; i += 256) st[i] = g_tsort[i];
  __syncthreads();
  int base = (blockIdx.x * 256 + t) * 4;
  float4 a4 = *(const float4*)&am[base];
  float av[4] = {a4.x, a4.y, a4.z, a4.w};
  unsigned short res[4];
#pragma unroll
  for (int u = 0; u < 4; u++) {
    int pos = 0;
#pragma unroll
    for (int sgm = 256; sgm >= 1; sgm >>= 1)
      if (st[pos + sgm - 1] < av[u]) pos += sgm;
    res[u] = (unsigned short)pos;
  }
  *(ushort4*)&g_sidx[base] = make_ushort4(res[0], res[1], res[2], res[3]);
}

// ---------------- fused attention: online softmax + f32x2 math -----------
// All float4/ulonglong2-accessed members at 16B-aligned offsets, before the
// odd-sized sF/sG tables.
struct AttnSmem {
  float sQ[8][32];         // @0      scaled Q tile (128B rows)
  float sK[256][36];       // @1024   K tile staging (144B rows, 16B-aligned)
  float sPt[256][12];      // @37888  per-tile probs (48B rows, 16B-aligned)
  float sRed[8][8];        // @50176  [qi][warp] partial max/sum
  float sF[RPE + 4];       // @50432
  float sG[RPE + 4];
};
// sOut (8KB) aliases sK after the last tile.

__global__ void __launch_bounds__(256, 4) attention(
    const float* __restrict__ pad, const float* __restrict__ am) {
  extern __shared__ char raw[];
  AttnSmem* S = (AttnSmem*)raw;
  const int h = blockIdx.y;
  const int q0 = blockIdx.x * 8;
  const int t = threadIdx.x;
  const int lane = t & 31, w = t >> 5;

  S->sQ[w][lane] = g_q[(q0 + w) * DIM + h * HD + lane] * SCALE;
  for (int i = t; i <= RPE; i += 256) {
    S->sF[i] = g_F[h * (RPE + 1) + i];
    S->sG[i] = g_G[h * (RPE + 1) + i];
  }

  unsigned long long out2[4];  // (qi even, qi odd) packed output accumulators
  float m[8], s[8];
#pragma unroll
  for (int p = 0; p < 4; p++) out2[p] = 0ull;
#pragma unroll
  for (int qi = 0; qi < 8; qi++) {
    s[qi] = 0.f;
    m[qi] = -INFINITY;
  }

#pragma unroll 1
  for (int tl = 0; tl < 4; tl++) {
    __syncthreads();  // prev tile done reading sK / sRed
    // ---- stage K tile (256 keys x 32 dims) ----
#pragma unroll
    for (int i = 0; i < 8; i++) {
      int j = t + i * 256;
      int rr = j >> 3, c = j & 7;
      *(float4*)&S->sK[rr][c * 4] =
          *(const float4*)&g_k[(tl * 256 + rr) * DIM + h * HD + c * 4];
    }
    const int kglob = tl * 256 + t;
    float padv = 100.f * __ldg(&pad[kglob]);
    __syncthreads();

    // ---- dots: d-packed f32x2, this thread's key vs 8 queries ----
    unsigned long long acc2[8];
#pragma unroll
    for (int qi = 0; qi < 8; qi++) acc2[qi] = 0ull;
#pragma unroll
    for (int c = 0; c < 8; c++) {
      ulonglong2 kv2 = *(const ulonglong2*)&S->sK[t][c * 4];
#pragma unroll
      for (int qi = 0; qi < 8; qi++) {
        ulonglong2 qv2 = *(const ulonglong2*)&S->sQ[qi][c * 4];
        fma2(acc2[qi], qv2.x, kv2.x);
        fma2(acc2[qi], qv2.y, kv2.y);
      }
    }
    float acc[8];
#pragma unroll
    for (int qi = 0; qi < 8; qi++) {
      float lo, hi;
      upk2(lo, hi, acc2[qi]);
      acc[qi] = lo + hi;
    }
    // ---- CPB bias + padding ----
#pragma unroll
    for (int qi = 0; qi < 8; qi++) {
      float a = __ldg(&am[(q0 + qi) * NK + kglob]);
      int ix = (int)g_sidx[(q0 + qi) * NK + kglob];
      acc[qi] += fmaf(a, S->sF[ix], S->sG[ix]) - padv;
    }

    // ---- block-wide tile max per query ----
    float tm[8];
#pragma unroll
    for (int qi = 0; qi < 8; qi++) tm[qi] = acc[qi];
#pragma unroll
    for (int o = 16; o; o >>= 1)
#pragma unroll
      for (int qi = 0; qi < 8; qi++)
        tm[qi] = fmaxf(tm[qi], __shfl_xor_sync(FULLMASK, tm[qi], o));
    if (lane == 0)
#pragma unroll
      for (int qi = 0; qi < 8; qi++) S->sRed[qi][w] = tm[qi];
    __syncthreads();

    // ---- online update: m, s, out rescale; probs in acc ----
    float fq[8];
#pragma unroll
    for (int qi = 0; qi < 8; qi++) {
      float4 r0 = *(const float4*)&S->sRed[qi][0];
      float4 r1 = *(const float4*)&S->sRed[qi][4];
      float mn = fmaxf(fmaxf(fmaxf(r0.x, r0.y), fmaxf(r0.z, r0.w)),
                       fmaxf(fmaxf(r1.x, r1.y), fmaxf(r1.z, r1.w)));
      mn = fmaxf(mn, m[qi]);
      fq[qi] = __expf(m[qi] - mn);
      m[qi] = mn;
      float e = __expf(acc[qi] - mn);
      s[qi] = s[qi] * fq[qi] + e;
      acc[qi] = e;
    }
#pragma unroll
    for (int p = 0; p < 4; p++) mul2(out2[p], pk2(fq[2 * p], fq[2 * p + 1]));

    // warp-private prob exchange (pairs (0,1)(2,3)(4,5)(6,7) in order)
    *(float4*)&S->sPt[t][0] = make_float4(acc[0], acc[1], acc[2], acc[3]);
    *(float4*)&S->sPt[t][4] = make_float4(acc[4], acc[5], acc[6], acc[7]);
    __syncwarp();

    // ---- AV: qi-packed f32x2; V straight from L2 ----
    const float* vb = &g_v[(tl * 256 + w * 32) * DIM + h * HD + lane];
#pragma unroll
    for (int jj = 0; jj < 32; jj++) {
      float vv = __ldg(&vb[jj * DIM]);
      unsigned long long vvp = pk2(vv, vv);
      ulonglong2 p01 = *(const ulonglong2*)&S->sPt[w * 32 + jj][0];
      ulonglong2 p23 = *(const ulonglong2*)&S->sPt[w * 32 + jj][4];
      fma2(out2[0], p01.x, vvp);
      fma2(out2[1], p01.y, vvp);
      fma2(out2[2], p23.x, vvp);
      fma2(out2[3], p23.y, vvp);
    }
  }

  // ---- final sum reduce + normalize + cross-warp output reduce ----
  __syncthreads();  // all warps done with tile-3 sRed reads
#pragma unroll
  for (int o = 16; o; o >>= 1)
#pragma unroll
    for (int qi = 0; qi < 8; qi++)
      s[qi] += __shfl_xor_sync(FULLMASK, s[qi], o);
  if (lane == 0)
#pragma unroll
    for (int qi = 0; qi < 8; qi++) S->sRed[qi][w] = s[qi];
  __syncthreads();

  float out[8];
#pragma unroll
  for (int p = 0; p < 4; p++) upk2(out[2 * p], out[2 * p + 1], out2[p]);

  float (*sOut)[8][32] = (float(*)[8][32])S->sK;  // alias
#pragma unroll
  for (int qi = 0; qi < 8; qi++) {
    float4 r0 = *(const float4*)&S->sRed[qi][0];
    float4 r1 = *(const float4*)&S->sRed[qi][4];
    float stot = (r0.x + r0.y) + (r0.z + r0.w) + (r1.x + r1.y) + (r1.z + r1.w);
    sOut[w][qi][lane] = out[qi] * (1.f / stot);
  }
  __syncthreads();
  {
    float accf = 0.f;
#pragma unroll
    for (int ww = 0; ww < 8; ww++) accf += sOut[ww][w][lane];
    g_x[(q0 + w) * DIM + h * HD + lane] = accf;
  }
}

// ---------------- launch ------------------------------------------------
extern "C" void kernel_launch(void* const* d_in, const int* in_sizes, int n_in,
                              void* d_out, int out_size) {
  const float* query = (const float*)d_in[0];
  const float* kin   = (const float*)d_in[1];
  const float* vin   = (const float*)d_in[2];
  const float* pad   = (const float*)d_in[3];
  const float* am    = (const float*)d_in[4];
  const float* Wq    = (const float*)d_in[5];
  const float* bq    = (const float*)d_in[6];
  const float* Wk    = (const float*)d_in[7];
  const float* bk    = (const float*)d_in[8];
  const float* Wv    = (const float*)d_in[9];
  const float* bv    = (const float*)d_in[10];
  const float* Wp    = (const float*)d_in[11];
  const float* bp    = (const float*)d_in[12];
  const float* W1    = (const float*)d_in[13];
  const float* b1    = (const float*)d_in[14];
  const float* W2    = (const float*)d_in[15];
  float* out = (float*)d_out;

  cudaFuncSetAttribute(attention, cudaFuncAttributeMaxDynamicSharedMemorySize,
                       (int)sizeof(AttnSmem));

  // Q/K/V projections: 32x64 tiles (x covers NK/32; Q tiles guard out)
  gemm32<<<dim3(32, 4, 3), 128>>>(query, kin, vin, Wq, bq, Wk, bk, Wv, bv,
                                  Wp, bp, out, 0);
  cpb_precompute<<<1, RPE>>>(W1, b1, W2);
  cpb_index<<<NQ * NK / 4 / 256, 256>>>(am);
  attention<<<dim3(NQ / 8, HEADS), 256, sizeof(AttnSmem)>>>(pad, am);
  // output projection
  gemm32<<<dim3(16, 4, 1), 128>>>(query, kin, vin, Wq, bq, Wk, bk, Wv, bv,
                                  Wp, bp, out, 3);
}

// round 7
// speedup vs baseline: 2.0238x; 1.1187x over previous
#include <cuda_runtime.h>
#include <math.h>

#define NQ 512
#define NK 1024
#define DIM 256
#define HEADS 8
#define HD 32
#define RPE 512
#define SCALE 0.17677669529663687f
#define FULLMASK 0xffffffffu

// ---------------- packed fp32x2 helpers ----------------------------------
__device__ __forceinline__ unsigned long long pk2(float lo, float hi) {
  unsigned long long r;
  asm("mov.b64 %0, {%1, %2};" : "=l"(r) : "f"(lo), "f"(hi));
  return r;
}
__device__ __forceinline__ void upk2(float& lo, float& hi, unsigned long long v) {
  asm("mov.b64 {%0, %1}, %2;" : "=f"(lo), "=f"(hi) : "l"(v));
}
__device__ __forceinline__ void fma2(unsigned long long& d, unsigned long long a,
                                     unsigned long long b) {
  asm("fma.rn.f32x2 %0, %1, %2, %0;" : "+l"(d) : "l"(a), "l"(b));
}

// ---------------- scratch (device globals; no allocation) ----------------
__device__ float g_q[NQ * DIM];
__device__ float g_kT[DIM * NK];  // K TRANSPOSED: [d][key]
__device__ float g_v[NK * DIM];
__device__ float g_x[NQ * DIM];
__device__ float g_tsort[RPE];
__device__ float g_F[HEADS * (RPE + 1)];
__device__ float g_G[HEADS * (RPE + 1)];
__device__ unsigned short g_sidx[NQ * NK];

// ---------------- GEMM 32x64 tiles, 128 threads, 4x4/thread --------------
// sel: 0 -> q proj, 1 -> k proj (TRANSPOSED store), 2 -> v, 3 -> out proj
__global__ void __launch_bounds__(128) gemm32(
    const float* __restrict__ query, const float* __restrict__ kin,
    const float* __restrict__ vin,
    const float* __restrict__ Wq, const float* __restrict__ bq,
    const float* __restrict__ Wk, const float* __restrict__ bk,
    const float* __restrict__ Wv, const float* __restrict__ bv,
    const float* __restrict__ Wp, const float* __restrict__ bp,
    float* __restrict__ outp, int selBase) {
  __shared__ float As[16][36];
  __shared__ float Bs[16][64];

  int sel = blockIdx.z + selBase;
  const float* A;
  const float* W;
  const float* bias;
  float* C;
  int M;
  if (sel == 0) { A = query; W = Wq; bias = bq; C = g_q; M = NQ; }
  else if (sel == 1) { A = kin; W = Wk; bias = bk; C = g_kT; M = NK; }
  else if (sel == 2) { A = vin; W = Wv; bias = bv; C = g_v; M = NK; }
  else { A = g_x; W = Wp; bias = bp; C = outp; M = NQ; }

  int bm = blockIdx.x * 32;
  if (bm >= M) return;
  int bn = blockIdx.y * 64;

  int t = threadIdx.x;
  int tx = t % 16, ty = t / 16;
  float acc[4][4] = {};

  for (int k0 = 0; k0 < 256; k0 += 16) {
    {
      int r = t >> 2, c4 = t & 3;
      float4 av = *(const float4*)&A[(bm + r) * 256 + k0 + c4 * 4];
      As[c4 * 4 + 0][r] = av.x;
      As[c4 * 4 + 1][r] = av.y;
      As[c4 * 4 + 2][r] = av.z;
      As[c4 * 4 + 3][r] = av.w;
    }
    {
#pragma unroll
      for (int u = 0; u < 2; u++) {
        int idx = t * 2 + u;
        int r = idx >> 4, c4 = idx & 15;
        *(float4*)&Bs[r][c4 * 4] = *(const float4*)&W[(k0 + r) * 256 + bn + c4 * 4];
      }
    }
    __syncthreads();
#pragma unroll
    for (int k = 0; k < 16; k++) {
      float a[4], b[4];
#pragma unroll
      for (int i = 0; i < 4; i++) a[i] = As[k][ty * 4 + i];
#pragma unroll
      for (int j = 0; j < 4; j++) b[j] = Bs[k][tx * 4 + j];
#pragma unroll
      for (int i = 0; i < 4; i++)
#pragma unroll
        for (int j = 0; j < 4; j++) acc[i][j] = fmaf(a[i], b[j], acc[i][j]);
    }
    __syncthreads();
  }
  if (sel == 1) {  // transposed: g_kT[col][row]
#pragma unroll
    for (int i = 0; i < 4; i++) {
      int row = bm + ty * 4 + i;
#pragma unroll
      for (int j = 0; j < 4; j++) {
        int col = bn + tx * 4 + j;
        C[col * NK + row] = acc[i][j] + bias[col];
      }
    }
  } else {
#pragma unroll
    for (int i = 0; i < 4; i++) {
      int row = bm + ty * 4 + i;
#pragma unroll
      for (int j = 0; j < 4; j++) {
        int col = bn + tx * 4 + j;
        C[row * 256 + col] = acc[i][j] + bias[col];
      }
    }
  }
}

// ---------------- CPB precompute: sort + shfl-based vector scans ---------
__global__ void __launch_bounds__(512) cpb_precompute(
    const float* __restrict__ W1v, const float* __restrict__ b1v,
    const float* __restrict__ W2v) {
  __shared__ float skey[RPE];
  __shared__ int sord[RPE];
  __shared__ float swtA[16][8];
  __shared__ float swtB[16][8];
  __shared__ float sF0[8], sG0[8];
  __shared__ float sTotW[8], sTotB[8];
  int t = threadIdx.x, lane = t & 31, warp = t >> 5;

  float w1 = W1v[t], bb = b1v[t];
  skey[t] = (w1 != 0.f) ? (-bb / w1) : INFINITY;
  sord[t] = t;
  __syncthreads();

  for (int size = 2; size <= RPE; size <<= 1) {
    for (int stride = size >> 1; stride > 0; stride >>= 1) {
      int p = t ^ stride;
      if (p > t) {
        bool asc = ((t & size) == 0);
        float k1 = skey[t], k2 = skey[p];
        if ((k1 > k2) == asc) {
          skey[t] = k2;
          skey[p] = k1;
          int tmp = sord[t];
          sord[t] = sord[p];
          sord[p] = tmp;
        }
      }
      __syncthreads();
    }
  }
  g_tsort[t] = skey[t];
  int r = sord[t];
  float w1r = W1v[r], b1r = b1v[r];
  bool isPos = (w1r > 0.f), isNeg = (w1r < 0.f);
  bool isZero = (!isPos && !isNeg);
  float sgn = isPos ? 1.f : (isNeg ? -1.f : 0.f);

  float ocw[8], ocb[8], cw[8], cb[8], f0[8], g0[8];
#pragma unroll
  for (int h = 0; h < 8; h++) {
    float w2 = W2v[r * HEADS + h];
    ocw[h] = sgn * w1r * w2;
    ocb[h] = sgn * b1r * w2;
    cw[h] = ocw[h];
    cb[h] = ocb[h];
    f0[h] = isNeg ? (w1r * w2) : 0.f;
    g0[h] = isNeg ? (b1r * w2) : ((isZero && b1r > 0.f) ? (b1r * w2) : 0.f);
  }

#pragma unroll
  for (int o = 16; o; o >>= 1)
#pragma unroll
    for (int h = 0; h < 8; h++) {
      f0[h] += __shfl_xor_sync(FULLMASK, f0[h], o);
      g0[h] += __shfl_xor_sync(FULLMASK, g0[h], o);
    }
  if (lane == 0)
#pragma unroll
    for (int h = 0; h < 8; h++) {
      swtA[warp][h] = f0[h];
      swtB[warp][h] = g0[h];
    }
  __syncthreads();
  if (t < 8) {
    float sa = 0.f, sb = 0.f;
    for (int ww = 0; ww < 16; ww++) {
      sa += swtA[ww][t];
      sb += swtB[ww][t];
    }
    sF0[t] = sa;
    sG0[t] = sb;
  }
  __syncthreads();

#pragma unroll
  for (int o = 1; o < 32; o <<= 1) {
#pragma unroll
    for (int h = 0; h < 8; h++) {
      float ta = __shfl_up_sync(FULLMASK, cw[h], o);
      float tb = __shfl_up_sync(FULLMASK, cb[h], o);
      if (lane >= o) {
        cw[h] += ta;
        cb[h] += tb;
      }
    }
  }
  if (lane == 31)
#pragma unroll
    for (int h = 0; h < 8; h++) {
      swtA[warp][h] = cw[h];
      swtB[warp][h] = cb[h];
    }
  __syncthreads();

  if (warp == 0) {
    float va[8], vb[8], owa[8], owb[8];
#pragma unroll
    for (int h = 0; h < 8; h++) {
      owa[h] = (lane < 16) ? swtA[lane][h] : 0.f;
      owb[h] = (lane < 16) ? swtB[lane][h] : 0.f;
      va[h] = owa[h];
      vb[h] = owb[h];
    }
#pragma unroll
    for (int o = 1; o < 16; o <<= 1)
#pragma unroll
      for (int h = 0; h < 8; h++) {
        float ta = __shfl_up_sync(FULLMASK, va[h], o);
        float tb = __shfl_up_sync(FULLMASK, vb[h], o);
        if (lane >= o) {
          va[h] += ta;
          vb[h] += tb;
        }
      }
    if (lane < 16) {
#pragma unroll
      for (int h = 0; h < 8; h++) {
        swtA[lane][h] = va[h] - owa[h];
        swtB[lane][h] = vb[h] - owb[h];
        if (lane == 15) {
          sTotW[h] = va[h];
          sTotB[h] = vb[h];
        }
      }
    }
  }
  __syncthreads();

#pragma unroll
  for (int h = 0; h < 8; h++) {
    float excl = (cw[h] - ocw[h]) + swtA[warp][h];
    float exclb = (cb[h] - ocb[h]) + swtB[warp][h];
    g_F[h * (RPE + 1) + t] = sF0[h] + excl;
    g_G[h * (RPE + 1) + t] = sG0[h] + exclb;
  }
  if (t == 0)
#pragma unroll
    for (int h = 0; h < 8; h++) {
      g_F[h * (RPE + 1) + RPE] = sF0[h] + sTotW[h];
      g_G[h * (RPE + 1) + RPE] = sG0[h] + sTotB[h];
    }
}

// ---------------- per-pair breakpoint index (branchless, x4) -------------
__global__ void __launch_bounds__(256) cpb_index(const float* __restrict__ am) {
  __shared__ float st[RPE];
  int t = threadIdx.x;
  for (int i = t; i < RPE; i += 256) st[i] = g_tsort[i];
  __syncthreads();
  int base = (blockIdx.x * 256 + t) * 4;
  float4 a4 = *(const float4*)&am[base];
  float av[4] = {a4.x, a4.y, a4.z, a4.w};
  unsigned short res[4];
#pragma unroll
  for (int u = 0; u < 4; u++) {
    int pos = 0;
#pragma unroll
    for (int sgm = 256; sgm >= 1; sgm >>= 1)
      if (st[pos + sgm - 1] < av[u]) pos += sgm;
    res[u] = (unsigned short)pos;
  }
  *(ushort4*)&g_sidx[base] = make_ushort4(res[0], res[1], res[2], res[3]);
}

// ---------------- fused attention: single-pass, reg-resident logits ------
// Thread t owns keys 4t..4t+3, all 8 queries. K read from g_kT (coalesced).
struct AttnSmem {
  float sQ[8][32];  // @0 (1KB)
  union {
    float sP[NK][8];       // 32KB: normalized probs
    float sOut[8][8][32];  // 8KB epilogue (aliases sP after AV)
  } u;                     // @1024
  float sRed[8][8];        // @33792
  float sF[RPE + 4];
  float sG[RPE + 4];
};

__global__ void __launch_bounds__(256, 4) attention(
    const float* __restrict__ pad, const float* __restrict__ am) {
  extern __shared__ char raw[];
  AttnSmem* S = (AttnSmem*)raw;
  const int h = blockIdx.y;
  const int q0 = blockIdx.x * 8;
  const int t = threadIdx.x;
  const int lane = t & 31, w = t >> 5;
  const int kbase = 4 * t;

  S->sQ[w][lane] = g_q[(q0 + w) * DIM + h * HD + lane] * SCALE;
  for (int i = t; i <= RPE; i += 256) {
    S->sF[i] = g_F[h * (RPE + 1) + i];
    S->sG[i] = g_G[h * (RPE + 1) + i];
  }
  __syncthreads();

  // ---- QK: acc[kg][qi], K via transposed coalesced LDG ----
  float acc[4][8];
#pragma unroll
  for (int kg = 0; kg < 4; kg++)
#pragma unroll
    for (int qi = 0; qi < 8; qi++) acc[kg][qi] = 0.f;

#pragma unroll
  for (int c = 0; c < 8; c++) {
    const float* kp = &g_kT[(h * HD + c * 4) * NK + kbase];
    float4 kq0 = *(const float4*)&kp[0 * NK];
    float4 kq1 = *(const float4*)&kp[1 * NK];
    float4 kq2 = *(const float4*)&kp[2 * NK];
    float4 kq3 = *(const float4*)&kp[3 * NK];
#pragma unroll
    for (int qi = 0; qi < 8; qi++) {
      float4 qv = *(const float4*)&S->sQ[qi][c * 4];
      acc[0][qi] = fmaf(qv.x, kq0.x, acc[0][qi]);
      acc[0][qi] = fmaf(qv.y, kq1.x, acc[0][qi]);
      acc[0][qi] = fmaf(qv.z, kq2.x, acc[0][qi]);
      acc[0][qi] = fmaf(qv.w, kq3.x, acc[0][qi]);
      acc[1][qi] = fmaf(qv.x, kq0.y, acc[1][qi]);
      acc[1][qi] = fmaf(qv.y, kq1.y, acc[1][qi]);
      acc[1][qi] = fmaf(qv.z, kq2.y, acc[1][qi]);
      acc[1][qi] = fmaf(qv.w, kq3.y, acc[1][qi]);
      acc[2][qi] = fmaf(qv.x, kq0.z, acc[2][qi]);
      acc[2][qi] = fmaf(qv.y, kq1.z, acc[2][qi]);
      acc[2][qi] = fmaf(qv.z, kq2.z, acc[2][qi]);
      acc[2][qi] = fmaf(qv.w, kq3.z, acc[2][qi]);
      acc[3][qi] = fmaf(qv.x, kq0.w, acc[3][qi]);
      acc[3][qi] = fmaf(qv.y, kq1.w, acc[3][qi]);
      acc[3][qi] = fmaf(qv.z, kq2.w, acc[3][qi]);
      acc[3][qi] = fmaf(qv.w, kq3.w, acc[3][qi]);
    }
  }

  // ---- CPB bias + padding (vectorized over the 4 owned keys) ----
  {
    float4 p4 = *(const float4*)&pad[kbase];
    float pv[4] = {100.f * p4.x, 100.f * p4.y, 100.f * p4.z, 100.f * p4.w};
#pragma unroll
    for (int qi = 0; qi < 8; qi++) {
      float4 a4 = *(const float4*)&am[(q0 + qi) * NK + kbase];
      ushort4 x4 = *(const ushort4*)&g_sidx[(q0 + qi) * NK + kbase];
      acc[0][qi] += fmaf(a4.x, S->sF[x4.x], S->sG[x4.x]) - pv[0];
      acc[1][qi] += fmaf(a4.y, S->sF[x4.y], S->sG[x4.y]) - pv[1];
      acc[2][qi] += fmaf(a4.z, S->sF[x4.z], S->sG[x4.z]) - pv[2];
      acc[3][qi] += fmaf(a4.w, S->sF[x4.w], S->sG[x4.w]) - pv[3];
    }
  }

  // ---- block max per query ----
  float m[8];
#pragma unroll
  for (int qi = 0; qi < 8; qi++)
    m[qi] = fmaxf(fmaxf(acc[0][qi], acc[1][qi]), fmaxf(acc[2][qi], acc[3][qi]));
#pragma unroll
  for (int o = 16; o; o >>= 1)
#pragma unroll
    for (int qi = 0; qi < 8; qi++)
      m[qi] = fmaxf(m[qi], __shfl_xor_sync(FULLMASK, m[qi], o));
  if (lane == 0)
#pragma unroll
    for (int qi = 0; qi < 8; qi++) S->sRed[qi][w] = m[qi];
  __syncthreads();
#pragma unroll
  for (int qi = 0; qi < 8; qi++) {
    float4 r0 = *(const float4*)&S->sRed[qi][0];
    float4 r1 = *(const float4*)&S->sRed[qi][4];
    m[qi] = fmaxf(fmaxf(fmaxf(r0.x, r0.y), fmaxf(r0.z, r0.w)),
                  fmaxf(fmaxf(r1.x, r1.y), fmaxf(r1.z, r1.w)));
  }

  // ---- exp + sum ----
  float s[8];
#pragma unroll
  for (int qi = 0; qi < 8; qi++) {
    float e0 = __expf(acc[0][qi] - m[qi]);
    float e1 = __expf(acc[1][qi] - m[qi]);
    float e2 = __expf(acc[2][qi] - m[qi]);
    float e3 = __expf(acc[3][qi] - m[qi]);
    acc[0][qi] = e0;
    acc[1][qi] = e1;
    acc[2][qi] = e2;
    acc[3][qi] = e3;
    s[qi] = (e0 + e1) + (e2 + e3);
  }
#pragma unroll
  for (int o = 16; o; o >>= 1)
#pragma unroll
    for (int qi = 0; qi < 8; qi++)
      s[qi] += __shfl_xor_sync(FULLMASK, s[qi], o);
  __syncthreads();  // all sRed max reads done
  if (lane == 0)
#pragma unroll
    for (int qi = 0; qi < 8; qi++) S->sRed[qi][w] = s[qi];
  __syncthreads();
  float inv[8];
#pragma unroll
  for (int qi = 0; qi < 8; qi++) {
    float4 r0 = *(const float4*)&S->sRed[qi][0];
    float4 r1 = *(const float4*)&S->sRed[qi][4];
    inv[qi] = 1.f / ((r0.x + r0.y) + (r0.z + r0.w) + (r1.x + r1.y) + (r1.z + r1.w));
  }

  // ---- store NORMALIZED probs: sP[key][qi] ----
#pragma unroll
  for (int kg = 0; kg < 4; kg++) {
    *(float4*)&S->u.sP[kbase + kg][0] =
        make_float4(acc[kg][0] * inv[0], acc[kg][1] * inv[1],
                    acc[kg][2] * inv[2], acc[kg][3] * inv[3]);
    *(float4*)&S->u.sP[kbase + kg][4] =
        make_float4(acc[kg][4] * inv[4], acc[kg][5] * inv[5],
                    acc[kg][6] * inv[6], acc[kg][7] * inv[7]);
  }
  __syncthreads();

  // ---- AV: warp owns keys [w*128, w*128+128); qi-packed f32x2 ----
  unsigned long long out2[4] = {0ull, 0ull, 0ull, 0ull};
  const float* vb = &g_v[(w * 128) * DIM + h * HD + lane];
#pragma unroll 8
  for (int jj = 0; jj < 128; jj++) {
    float vv = __ldg(&vb[jj * DIM]);
    unsigned long long vvp = pk2(vv, vv);
    ulonglong2 p01 = *(const ulonglong2*)&S->u.sP[w * 128 + jj][0];
    ulonglong2 p23 = *(const ulonglong2*)&S->u.sP[w * 128 + jj][4];
    fma2(out2[0], p01.x, vvp);
    fma2(out2[1], p01.y, vvp);
    fma2(out2[2], p23.x, vvp);
    fma2(out2[3], p23.y, vvp);
  }
  __syncthreads();  // all sP reads done before sOut alias write

  float out[8];
#pragma unroll
  for (int p = 0; p < 4; p++) upk2(out[2 * p], out[2 * p + 1], out2[p]);
#pragma unroll
  for (int qi = 0; qi < 8; qi++) S->u.sOut[w][qi][lane] = out[qi];
  __syncthreads();
  {
    float accf = 0.f;
#pragma unroll
    for (int ww = 0; ww < 8; ww++) accf += S->u.sOut[ww][w][lane];
    g_x[(q0 + w) * DIM + h * HD + lane] = accf;
  }
}

// ---------------- launch ------------------------------------------------
extern "C" void kernel_launch(void* const* d_in, const int* in_sizes, int n_in,
                              void* d_out, int out_size) {
  const float* query = (const float*)d_in[0];
  const float* kin   = (const float*)d_in[1];
  const float* vin   = (const float*)d_in[2];
  const float* pad   = (const float*)d_in[3];
  const float* am    = (const float*)d_in[4];
  const float* Wq    = (const float*)d_in[5];
  const float* bq    = (const float*)d_in[6];
  const float* Wk    = (const float*)d_in[7];
  const float* bk    = (const float*)d_in[8];
  const float* Wv    = (const float*)d_in[9];
  const float* bv    = (const float*)d_in[10];
  const float* Wp    = (const float*)d_in[11];
  const float* bp    = (const float*)d_in[12];
  const float* W1    = (const float*)d_in[13];
  const float* b1    = (const float*)d_in[14];
  const float* W2    = (const float*)d_in[15];
  float* out = (float*)d_out;

  cudaFuncSetAttribute(attention, cudaFuncAttributeMaxDynamicSharedMemorySize,
                       (int)sizeof(AttnSmem));

  gemm32<<<dim3(32, 4, 3), 128>>>(query, kin, vin, Wq, bq, Wk, bk, Wv, bv,
                                  Wp, bp, out, 0);
  cpb_precompute<<<1, RPE>>>(W1, b1, W2);
  cpb_index<<<NQ * NK / 4 / 256, 256>>>(am);
  attention<<<dim3(NQ / 8, HEADS), 256, sizeof(AttnSmem)>>>(pad, am);
  gemm32<<<dim3(16, 4, 1), 128>>>(query, kin, vin, Wq, bq, Wk, bk, Wv, bv,
                                  Wp, bp, out, 3);
}